// round 8
// baseline (speedup 1.0000x reference)
#include <cuda_runtime.h>

// RandomShiftsAug == integer shifted gather with edge clamp:
//   out[n,c,j,i] = x[n,c, clamp(j+sy-4,0,83), clamp(i+sx-4,0,83)]
//
// R8: fully-aligned 128-bit traffic on BOTH sides. sx is uniform per block
// (shift is per-n, block = one (n,c) slice), so we dispatch switch(sx) into
// 9 compile-time specializations. Each output float4 (cols 4q..4q+3) is built
// from two ALIGNED source float4s src4[w], src4[w+1] (w=(4q+sx)>>2) with a
// static component rotation r = sx&3; edge replication (col0/col83) becomes
// static selects on q==0 / q==20. 3 memory instructions per 16B instead of 8.

#define N_   512
#define C_   9
#define H_   84
#define W_   84
#define PAD_ 4

#define W4      21              // float4 chunks per row
#define SLICE4  (H_ * W4)       // 1764 float4 per slice
#define THREADS 252             // 21 chunks x 12 row-phases
#define KITER   7               // 84 rows / 12 phases

template<int SX>
__device__ __forceinline__ void run_slice(const float4* __restrict__ src4,
                                          float4*       __restrict__ dst4,
                                          int q, int j0, int sy)
{
    constexpr int R = SX & 3;                      // component rotation
    const int w   = (4 * q + SX) >> 2;             // aligned window (floor div)
    const int iw0 = min(max(w,     0), W4 - 1);
    const int iw1 = min(max(w + 1, 0), W4 - 1);

    #pragma unroll
    for (int k = 0; k < KITER; k++) {
        const int j    = j0 + 12 * k;                       // output row
        const int srcy = min(max(j + sy, 0), H_ - 1);
        const float4* __restrict__ row = src4 + srcy * W4;

        const float4 a = __ldg(row + iw0);
        float4 c;
        if constexpr (R != 0) c = __ldg(row + iw1);
        else                  c = a;                        // unused components

        // static rotation: out_t = concat(a,c)[R + t]
        const float e0 = a.x, e1 = a.y, e2 = a.z, e3 = a.w;
        const float e4 = c.x, e5 = c.y, e6 = c.z, e7 = c.w;
        float4 o;
        if constexpr (R == 0)      { o.x = e0; o.y = e1; o.z = e2; o.w = e3; }
        else if constexpr (R == 1) { o.x = e1; o.y = e2; o.z = e3; o.w = e4; }
        else if constexpr (R == 2) { o.x = e2; o.y = e3; o.z = e4; o.w = e5; }
        else                       { o.x = e3; o.y = e4; o.z = e5; o.w = e6; }

        // edge replication (compile-time pruned per SX)
        if constexpr (SX < 0) {
            // cols 4q+SX+t < 0 only possible at q==0; col0 = a.x (iw0 clamped to 0)
            if (q == 0) {
                if constexpr (SX + 0 < 0) o.x = e0;
                if constexpr (SX + 1 < 0) o.y = e0;
                if constexpr (SX + 2 < 0) o.z = e0;
                if constexpr (SX + 3 < 0) o.w = e0;
            }
        }
        if constexpr (SX > 0) {
            // cols 4q+SX+t > 83 only possible at q==W4-1; col83 = src4[20].w
            if (q == W4 - 1) {
                const float c83 = (R == 0) ? e3 : e7;   // iw0==20 : iw1==20
                if constexpr (SX + 3 > 3) o.w = c83;
                if constexpr (SX + 2 > 3) o.z = c83;
                if constexpr (SX + 1 > 3) o.y = c83;
                if constexpr (SX + 0 > 3) o.x = c83;
            }
        }

        __stcs(dst4 + j * W4 + q, o);
    }
}

__global__ __launch_bounds__(THREADS, 6) void random_shift_vec_kernel(
    const float* __restrict__ x,
    const int*   __restrict__ shift,
    float*       __restrict__ out)
{
    const int nc  = blockIdx.x;            // (n*C + c)
    const int n   = nc / C_;
    const int tid = threadIdx.x;

    const int q  = tid % W4;               // output float4 chunk, 0..20
    const int j0 = tid / W4;               // row phase, 0..11

    const int sx = __ldg(&shift[2 * n + 0]) - PAD_;   // [-4, 4], block-uniform
    const int sy = __ldg(&shift[2 * n + 1]) - PAD_;

    const float4* __restrict__ src4 = reinterpret_cast<const float4*>(x)   + (long)nc * SLICE4;
    float4*       __restrict__ dst4 = reinterpret_cast<float4*>(out)       + (long)nc * SLICE4;

    switch (sx) {                          // uniform branch per block
        case -4: run_slice<-4>(src4, dst4, q, j0, sy); break;
        case -3: run_slice<-3>(src4, dst4, q, j0, sy); break;
        case -2: run_slice<-2>(src4, dst4, q, j0, sy); break;
        case -1: run_slice<-1>(src4, dst4, q, j0, sy); break;
        case  0: run_slice< 0>(src4, dst4, q, j0, sy); break;
        case  1: run_slice< 1>(src4, dst4, q, j0, sy); break;
        case  2: run_slice< 2>(src4, dst4, q, j0, sy); break;
        case  3: run_slice< 3>(src4, dst4, q, j0, sy); break;
        default: run_slice< 4>(src4, dst4, q, j0, sy); break;
    }
}

extern "C" void kernel_launch(void* const* d_in, const int* in_sizes, int n_in,
                              void* d_out, int out_size)
{
    const float* x     = (const float*)d_in[0];
    const int*   shift = (const int*)  d_in[1];
    float* out = (float*)d_out;

    random_shift_vec_kernel<<<N_ * C_, THREADS>>>(x, shift, out);
}

// round 9
// speedup vs baseline: 1.0049x; 1.0049x over previous
#include <cuda_runtime.h>

// RandomShiftsAug == integer shifted gather with edge clamp:
//   out[n,c,j,i] = x[n,c, clamp(j+sy-4,0,83), clamp(i+sx-4,0,83)]
//
// R8: fully-aligned 128-bit traffic on BOTH sides. sx is uniform per block
// (shift is per-n, block = one (n,c) slice), so we dispatch switch(sx) into
// 9 compile-time specializations. Each output float4 (cols 4q..4q+3) is built
// from two ALIGNED source float4s src4[w], src4[w+1] (w=(4q+sx)>>2) with a
// static component rotation r = sx&3; edge replication (col0/col83) becomes
// static selects on q==0 / q==20. 3 memory instructions per 16B instead of 8.

#define N_   512
#define C_   9
#define H_   84
#define W_   84
#define PAD_ 4

#define W4      21              // float4 chunks per row
#define SLICE4  (H_ * W4)       // 1764 float4 per slice
#define THREADS 252             // 21 chunks x 12 row-phases
#define KITER   7               // 84 rows / 12 phases

template<int SX>
__device__ __forceinline__ void run_slice(const float4* __restrict__ src4,
                                          float4*       __restrict__ dst4,
                                          int q, int j0, int sy)
{
    constexpr int R = SX & 3;                      // component rotation
    const int w   = (4 * q + SX) >> 2;             // aligned window (floor div)
    const int iw0 = min(max(w,     0), W4 - 1);
    const int iw1 = min(max(w + 1, 0), W4 - 1);

    #pragma unroll
    for (int k = 0; k < KITER; k++) {
        const int j    = j0 + 12 * k;                       // output row
        const int srcy = min(max(j + sy, 0), H_ - 1);
        const float4* __restrict__ row = src4 + srcy * W4;

        const float4 a = __ldg(row + iw0);
        float4 c;
        if constexpr (R != 0) c = __ldg(row + iw1);
        else                  c = a;                        // unused components

        // static rotation: out_t = concat(a,c)[R + t]
        const float e0 = a.x, e1 = a.y, e2 = a.z, e3 = a.w;
        const float e4 = c.x, e5 = c.y, e6 = c.z, e7 = c.w;
        float4 o;
        if constexpr (R == 0)      { o.x = e0; o.y = e1; o.z = e2; o.w = e3; }
        else if constexpr (R == 1) { o.x = e1; o.y = e2; o.z = e3; o.w = e4; }
        else if constexpr (R == 2) { o.x = e2; o.y = e3; o.z = e4; o.w = e5; }
        else                       { o.x = e3; o.y = e4; o.z = e5; o.w = e6; }

        // edge replication (compile-time pruned per SX)
        if constexpr (SX < 0) {
            // cols 4q+SX+t < 0 only possible at q==0; col0 = a.x (iw0 clamped to 0)
            if (q == 0) {
                if constexpr (SX + 0 < 0) o.x = e0;
                if constexpr (SX + 1 < 0) o.y = e0;
                if constexpr (SX + 2 < 0) o.z = e0;
                if constexpr (SX + 3 < 0) o.w = e0;
            }
        }
        if constexpr (SX > 0) {
            // cols 4q+SX+t > 83 only possible at q==W4-1; col83 = src4[20].w
            if (q == W4 - 1) {
                const float c83 = (R == 0) ? e3 : e7;   // iw0==20 : iw1==20
                if constexpr (SX + 3 > 3) o.w = c83;
                if constexpr (SX + 2 > 3) o.z = c83;
                if constexpr (SX + 1 > 3) o.y = c83;
                if constexpr (SX + 0 > 3) o.x = c83;
            }
        }

        __stcs(dst4 + j * W4 + q, o);
    }
}

__global__ __launch_bounds__(THREADS, 6) void random_shift_vec_kernel(
    const float* __restrict__ x,
    const int*   __restrict__ shift,
    float*       __restrict__ out)
{
    const int nc  = blockIdx.x;            // (n*C + c)
    const int n   = nc / C_;
    const int tid = threadIdx.x;

    const int q  = tid % W4;               // output float4 chunk, 0..20
    const int j0 = tid / W4;               // row phase, 0..11

    const int sx = __ldg(&shift[2 * n + 0]) - PAD_;   // [-4, 4], block-uniform
    const int sy = __ldg(&shift[2 * n + 1]) - PAD_;

    const float4* __restrict__ src4 = reinterpret_cast<const float4*>(x)   + (long)nc * SLICE4;
    float4*       __restrict__ dst4 = reinterpret_cast<float4*>(out)       + (long)nc * SLICE4;

    switch (sx) {                          // uniform branch per block
        case -4: run_slice<-4>(src4, dst4, q, j0, sy); break;
        case -3: run_slice<-3>(src4, dst4, q, j0, sy); break;
        case -2: run_slice<-2>(src4, dst4, q, j0, sy); break;
        case -1: run_slice<-1>(src4, dst4, q, j0, sy); break;
        case  0: run_slice< 0>(src4, dst4, q, j0, sy); break;
        case  1: run_slice< 1>(src4, dst4, q, j0, sy); break;
        case  2: run_slice< 2>(src4, dst4, q, j0, sy); break;
        case  3: run_slice< 3>(src4, dst4, q, j0, sy); break;
        default: run_slice< 4>(src4, dst4, q, j0, sy); break;
    }
}

extern "C" void kernel_launch(void* const* d_in, const int* in_sizes, int n_in,
                              void* d_out, int out_size)
{
    const float* x     = (const float*)d_in[0];
    const int*   shift = (const int*)  d_in[1];
    float* out = (float*)d_out;

    random_shift_vec_kernel<<<N_ * C_, THREADS>>>(x, shift, out);
}